// round 1
// baseline (speedup 1.0000x reference)
#include <cuda_runtime.h>
#include <cstdint>

// MaxUnpooling2D: updates [16,64,64,256] f32, mask int32 (flat index into
// [16,128,128,256]). Mask construction guarantees each pooled cell targets a
// position inside its own 2x2 window, so the scatter is a gather:
//   out[b,y,x,c] = (mask[b,y>>1,x>>1,c] == flatIdx(b,y,x,c)) ? updates[b,y>>1,x>>1,c] : 0
//
// All dims are powers of two:
//   B=16, H=W=64, C=256, H2=W2=128.
// Work in float4 granularity: 64 float4 per c-row.
//   idx (float4 id) layout: b(4b) | y(7b) | x(7b) | c4(6b)  -> 24 bits, 16.7M threads
//   input float4 index: b(4b) | h(6b) | w(6b) | c4(6b)

__global__ __launch_bounds__(256, 8)
void max_unpool_gather(const float4* __restrict__ upd4,
                       const int4* __restrict__ msk4,
                       float4* __restrict__ out4)
{
    unsigned idx = blockIdx.x * 256u + threadIdx.x;   // 0 .. 2^24-1

    unsigned c4 = idx & 63u;          // float4 lane within c-row
    unsigned x  = (idx >> 6) & 127u;  // output x
    unsigned y  = (idx >> 13) & 127u; // output y
    unsigned b  = idx >> 20;          // batch

    unsigned h = y >> 1;
    unsigned w = x >> 1;

    // input float4 index: ((b*64 + h)*64 + w)*64 + c4
    unsigned in4 = (((b << 6) | h) << 12) | (w << 6) | c4;

    int4   m = __ldg(&msk4[in4]);
    float4 u = __ldg(&upd4[in4]);

    int flat = (int)(idx << 2);       // flat element index of .x component

    float4 r;
    r.x = (m.x == flat    ) ? u.x : 0.0f;
    r.y = (m.y == flat + 1) ? u.y : 0.0f;
    r.z = (m.z == flat + 2) ? u.z : 0.0f;
    r.w = (m.w == flat + 3) ? u.w : 0.0f;

    out4[idx] = r;
}

extern "C" void kernel_launch(void* const* d_in, const int* in_sizes, int n_in,
                              void* d_out, int out_size)
{
    const float4* upd4 = (const float4*)d_in[0];
    const int4*   msk4 = (const int4*)d_in[1];
    float4*       out4 = (float4*)d_out;

    // out_size = 16*128*128*256 = 67108864 elements -> 16777216 float4
    const unsigned n4 = 16u * 128u * 128u * 64u;
    dim3 grid(n4 / 256u);
    max_unpool_gather<<<grid, 256>>>(upd4, msk4, out4);
}

// round 3
// speedup vs baseline: 1.1558x; 1.1558x over previous
#include <cuda_runtime.h>
#include <cstdint>

// MaxUnpooling2D as a gather, 4 outputs per thread.
// updates/mask: [16,64,64,256] f32/i32; out: [16,128,128,256] f32.
// Mask semantics guarantee each pooled cell targets exactly one slot of its
// own 2x2 window, so: out[b,y,x,c] = (mask[b,y>>1,x>>1,c]==flat(b,y,x,c)) ? upd : 0.
//
// Thread id layout (float4 granularity): b(4) | h(6) | w(6) | c4(6) = 22 bits
//   -> input float4 index == thread idx (loads need zero address math).
// Output float4 base: o00 = b<<20 | h<<14 | w<<7 | c4
//   x+1 -> +64 float4,  y+1 -> +8192 float4.

__global__ __launch_bounds__(256, 8)
void max_unpool_gather4(const float4* __restrict__ upd4,
                        const int4* __restrict__ msk4,
                        float4* __restrict__ out4)
{
    unsigned idx = blockIdx.x * 256u + threadIdx.x;   // 0 .. 2^22-1

    // Input loads first: address == idx, maximal MLP.
    int4   m = __ldg(&msk4[idx]);
    float4 u = __ldg(&upd4[idx]);

    unsigned c4 = idx & 63u;
    unsigned w  = (idx >> 6) & 63u;
    unsigned h  = (idx >> 12) & 63u;
    unsigned b  = idx >> 18;

    unsigned o00 = (b << 20) | (h << 14) | (w << 7) | c4;

    #pragma unroll
    for (int dy = 0; dy < 2; ++dy) {
        #pragma unroll
        for (int dx = 0; dx < 2; ++dx) {
            unsigned o = o00 + (unsigned)(dy * 8192 + dx * 64);
            int f = (int)(o << 2);          // flat element index of .x
            float4 r;
            r.x = (m.x == f    ) ? u.x : 0.0f;
            r.y = (m.y == f + 1) ? u.y : 0.0f;
            r.z = (m.z == f + 2) ? u.z : 0.0f;
            r.w = (m.w == f + 3) ? u.w : 0.0f;
            __stcs(&out4[o], r);            // write-once: evict-first
        }
    }
}

extern "C" void kernel_launch(void* const* d_in, const int* in_sizes, int n_in,
                              void* d_out, int out_size)
{
    const float4* upd4 = (const float4*)d_in[0];
    const int4*   msk4 = (const int4*)d_in[1];
    float4*       out4 = (float4*)d_out;

    // 16*64*64*64 = 4,194,304 threads, 4 output float4 each.
    dim3 grid(4194304u / 256u);
    max_unpool_gather4<<<grid, 256>>>(upd4, msk4, out4);
}